// round 11
// baseline (speedup 1.0000x reference)
#include <cuda_runtime.h>
#include <cuda_fp16.h>
#include <math.h>
#include <cstdint>

#define B_TOTAL 131072
#define SD 128
#define AD 32
#define TILE_M 128
#define NTILES 1024            // per branch
#define NTHREADS 512

__device__ float d_M[2][256];
// fp16 B fragments GEMM1: [br][ks(10)][ntile(32)][lane(32)][2 regs] as half2
__device__ __half2 d_Bfrag[2 * 10 * 32 * 32 * 2];
// fp16 B fragments GEMM2 (W2^T, n=8 padded): [br][ks(16)][lane(32)][2] half2
__device__ __half2 d_W2frag[2 * 16 * 32 * 2];
// dynamic tile counters per branch (reset by setup_kernel every launch)
__device__ int d_tilectr[2];

// ---- smem layout (byte offsets), one CTA/SM ----
#define OFF_B     0            // 81920B
#define OFF_A0    81920        // [128][168] halfs = 43008B
#define OFF_A1    124928       // 43008B
#define OFF_W2F   167936       // 4096B
#define OFF_B1S   172032       // 1024B
#define OFF_MS    173056       // 1152B (16x17 floats)
#define OFF_QPART 174208       // [4][128][4] floats = 8192B
#define OFF_B2S   182400       // 16B
#define OFF_PP    182416       // 8B
#define OFF_TID   182424       // 8B
#define SMEM_BYTES 182432

#define A_PITCH 168            // halfs per row
#define A_PITCH_B 336          // bytes

__device__ __forceinline__ uint32_t smem_u32(const void* p) {
    uint32_t a;
    asm("{ .reg .u64 t; cvta.to.shared.u64 t, %1; cvt.u32.u64 %0, t; }" : "=r"(a) : "l"(p));
    return a;
}
#define CP_ASYNC16(dst, src) \
    asm volatile("cp.async.cg.shared.global [%0], [%1], 16;" :: "r"(dst), "l"(src) : "memory")
#define CP_COMMIT() asm volatile("cp.async.commit_group;" ::: "memory")
#define CP_WAIT0()  asm volatile("cp.async.wait_group 0;" ::: "memory")

#define LDSM_X4(r0, r1, r2, r3, addr) \
    asm volatile("ldmatrix.sync.aligned.m8n8.x4.shared.b16 {%0,%1,%2,%3}, [%4];" \
        : "=r"(r0), "=r"(r1), "=r"(r2), "=r"(r3) : "r"(addr))

__device__ __forceinline__ void mma_f16(float* d, const uint32_t* a,
                                        uint32_t b0, uint32_t b1) {
    asm volatile(
        "mma.sync.aligned.m16n8k16.row.col.f32.f16.f16.f32 "
        "{%0,%1,%2,%3}, {%4,%5,%6,%7}, {%8,%9}, {%0,%1,%2,%3};"
        : "+f"(d[0]), "+f"(d[1]), "+f"(d[2]), "+f"(d[3])
        : "r"(a[0]), "r"(a[1]), "r"(a[2]), "r"(a[3]), "r"(b0), "r"(b1));
}
__device__ __forceinline__ uint32_t h2u(__half2 h) { return *(uint32_t*)&h; }

// ---------------------------------------------------------------------------
// Setup: blocks 0,1 -> M; 2..81 -> W1 frags; 82 -> W2 frags + counter reset.
// ---------------------------------------------------------------------------
__global__ void setup_kernel(const float* __restrict__ qw1,
                             const float* __restrict__ qw2,
                             const float* __restrict__ W1a,
                             const float* __restrict__ W1b,
                             const float* __restrict__ W2a,
                             const float* __restrict__ W2b) {
    if (blockIdx.x < 2) {
        const int br = blockIdx.x;
        const int t  = threadIdx.x;
        const int j  = t >> 4;
        const int m  = t & 15;
        const float* qw = br ? qw2 : qw1;
        __shared__ float Ur[16][17];
        __shared__ float Ui[16][17];

        float sr = (m == j) ? 1.f : 0.f;
        float si = 0.f;

        for (int l = 0; l < 2; ++l) {
            #pragma unroll
            for (int i = 0; i < 4; ++i) {
                const int st = 8 >> i;
                float cc, ss, pr, pi;
                sincosf(0.5f * qw[(l * 4 + i) * 3 + 0], &ss, &cc);   // RX
                pr = __shfl_xor_sync(0xffffffffu, sr, st);
                pi = __shfl_xor_sync(0xffffffffu, si, st);
                { float nr = cc * sr + ss * pi, ni = cc * si - ss * pr;
                  sr = nr; si = ni; }
                sincosf(0.5f * qw[(l * 4 + i) * 3 + 1], &ss, &cc);   // RY
                pr = __shfl_xor_sync(0xffffffffu, sr, st);
                pi = __shfl_xor_sync(0xffffffffu, si, st);
                { const float e = (m & st) ? ss : -ss;
                  float nr = cc * sr + e * pr, ni = cc * si + e * pi;
                  sr = nr; si = ni; }
                sincosf(0.5f * qw[(l * 4 + i) * 3 + 2], &ss, &cc);   // RZ
                { const float e = (m & st) ? -ss : ss;
                  float nr = cc * sr + e * si, ni = cc * si - e * sr;
                  sr = nr; si = ni; }
            }
            #pragma unroll
            for (int e = 0; e < 4; ++e) {
                const int sc  = 8 >> e;
                const int stt = 8 >> ((e + 1) & 3);
                const float pr = __shfl_xor_sync(0xffffffffu, sr, stt);
                const float pi = __shfl_xor_sync(0xffffffffu, si, stt);
                if (m & sc) { sr = pr; si = pi; }
            }
        }
        Ur[m][j] = sr;
        Ui[m][j] = si;
        __syncthreads();
        {
            const int i = t >> 4, jj = t & 15;
            float acc = 0.f;
            #pragma unroll
            for (int k = 0; k < 16; ++k) {
                const float d = (k < 8) ? 1.f : -1.f;
                acc += d * (Ur[k][i] * Ur[k][jj] + Ui[k][i] * Ui[k][jj]);
            }
            d_M[br][i * 16 + jj] = acc;
        }
    } else if (blockIdx.x < 82) {
        const int idx = (blockIdx.x - 2) * 256 + threadIdx.x;
        const int lane  = idx & 31;
        const int ntile = (idx >> 5) & 31;
        const int t     = idx >> 10;       // br*10 + ks
        const int ks    = t % 10;
        const int br    = t / 10;
        const float* W1 = br ? W1b : W1a;
        const int n  = ntile * 8 + (lane >> 2);
        const int k0 = ks * 16 + (lane & 3) * 2;
        d_Bfrag[idx * 2]     = __floats2half2_rn(W1[n * 160 + k0],     W1[n * 160 + k0 + 1]);
        d_Bfrag[idx * 2 + 1] = __floats2half2_rn(W1[n * 160 + k0 + 8], W1[n * 160 + k0 + 9]);
    } else {
        if (threadIdx.x == 0) { d_tilectr[0] = 0; d_tilectr[1] = 0; }
        #pragma unroll
        for (int rep = 0; rep < 4; ++rep) {
            const int idx = threadIdx.x + rep * 256;   // 0..1023
            const int br   = idx >> 9;
            const int rem  = idx & 511;
            const int ks   = rem >> 5;
            const int lane = rem & 31;
            const float* W2 = br ? W2b : W2a;
            const int n  = lane >> 2;
            const int k0 = ks * 16 + (lane & 3) * 2;
            __half2 v0 = __floats2half2_rn(0.f, 0.f), v1 = v0;
            if (n < 4) {
                v0 = __floats2half2_rn(W2[n * 256 + k0],     W2[n * 256 + k0 + 1]);
                v1 = __floats2half2_rn(W2[n * 256 + k0 + 8], W2[n * 256 + k0 + 9]);
            }
            d_W2frag[idx * 2]     = v0;
            d_W2frag[idx * 2 + 1] = v1;
        }
    }
}

// ---------------------------------------------------------------------------
// Persistent fused critic: 1 CTA/SM, 512 threads, double-buffered A with
// staging folded into the mainloop; 2 barriers/tile; dynamic tiles.
// ---------------------------------------------------------------------------
__global__ __launch_bounds__(NTHREADS, 1)
void critic_mma(const float* __restrict__ state,
                const float* __restrict__ action,
                const float* __restrict__ b1a, const float* __restrict__ b2a,
                const float* __restrict__ b1b, const float* __restrict__ b2b,
                const float* __restrict__ pwa, const float* __restrict__ pba,
                const float* __restrict__ pwb, const float* __restrict__ pbb,
                float* __restrict__ out) {
    extern __shared__ char smem[];
    const uint32_t sb = smem_u32(smem);
    const int tid  = threadIdx.x;
    const int w    = tid >> 5;
    const int lane = tid & 31;
    const int mw   = w >> 2;        // 0..3 row-warp
    const int nw   = w & 3;         // 0..3 col-warp
    const int gid  = lane >> 2;
    const int tig  = lane & 3;

    const int br = blockIdx.x & 1;

    const float* b1 = br ? b1b : b1a;
    const float* b2 = br ? b2b : b2a;
    const float* pw = br ? pwb : pwa;
    const float* pb = br ? pbb : pba;

    float* b1s   = (float*)(smem + OFF_B1S);
    float* Ms    = (float*)(smem + OFF_MS);      // pitch 17
    float* qpart = (float*)(smem + OFF_QPART);
    float* b2s   = (float*)(smem + OFF_B2S);
    float* pp    = (float*)(smem + OFF_PP);
    int*   stile = (int*)(smem + OFF_TID);

    // --- A staging: 128 x 160 fp32; 10 LDG.128 / 10 STS.64 per thread ---
    float4 aregs[10];
    auto ldgA = [&](int tile) {
        const int rowbase = (tile < NTILES ? tile : NTILES - 1) * TILE_M;
        #pragma unroll
        for (int ch = 0; ch < 5; ++ch)
            #pragma unroll
            for (int i = 0; i < 2; ++i) {
                const int e = tid + i * NTHREADS;     // 0..1023
                const int r = e >> 3, seg = e & 7;    // 128 rows x 8 segs
                const float* src = (ch < 4)
                    ? state  + (size_t)(rowbase + r) * SD + ch * 32 + seg * 4
                    : action + (size_t)(rowbase + r) * AD + seg * 4;
                aregs[ch * 2 + i] = *(const float4*)src;
            }
    };
    auto stsA_chunk = [&](__half* As, int k) {      // k = 0..9
        const int ch = k >> 1, i = k & 1;
        const int e = tid + i * NTHREADS;
        const int r = e >> 3, seg = e & 7;
        const float4 v = aregs[ch * 2 + i];
        __half2 h0 = __floats2half2_rn(v.x, v.y);
        __half2 h1 = __floats2half2_rn(v.z, v.w);
        *(uint2*)(As + r * A_PITCH + ch * 32 + seg * 4) =
            make_uint2(h2u(h0), h2u(h1));
    };

    // --- prologue ---
    {
        const __half2* srcB = d_Bfrag + (size_t)br * 20480;
        #pragma unroll
        for (int i = 0; i < 10; ++i) {
            const int e = tid + i * NTHREADS;         // 0..5119 16B segs
            CP_ASYNC16(sb + OFF_B + e * 16, srcB + e * 4);
        }
        if (tid < 256)
            CP_ASYNC16(sb + OFF_W2F + tid * 16, d_W2frag + br * 1024 + tid * 4);
        CP_COMMIT();
    }
    if (tid == 0) {
        stile[0] = atomicAdd(&d_tilectr[br], 1);
        stile[1] = atomicAdd(&d_tilectr[br], 1);
    }
    if (tid < 256) {
        b1s[tid] = b1[tid];
        Ms[(tid >> 4) * 17 + (tid & 15)] = d_M[br][tid];
    }
    if (tid < 4) b2s[tid] = b2[tid];
    if (tid == 0) { pp[0] = pw[0]; pp[1] = pb[0]; }
    __syncthreads();

    int cur = stile[0];
    int nxt = stile[1];
    if (cur >= NTILES) return;

    ldgA(cur);
    {
        __half* A0 = (__half*)(smem + OFF_A0);
        #pragma unroll
        for (int k = 0; k < 10; ++k) stsA_chunk(A0, k);
    }
    ldgA(nxt);
    CP_WAIT0();
    __syncthreads();

    const char* Bs   = smem + OFF_B;
    const char* W2Fs = smem + OFF_W2F;

    // ldmatrix per-lane address pieces
    const uint32_t lrow  = (lane & 7) + (((lane >> 3) & 1) << 3);
    const uint32_t lkofs = (lane >> 4) * 16;   // bytes
    const uint32_t AbBase = (mw * 32 + lrow) * A_PITCH_B + lkofs;

    int p = 0;
    while (true) {
        const int rowbase = cur * TILE_M;
        const uint32_t Ab = sb + (p ? OFF_A1 : OFF_A0) + AbBase;
        __half* Aother = (__half*)(smem + (p ? OFF_A0 : OFF_A1));

        float acc[2][8][4];
        #pragma unroll
        for (int mt = 0; mt < 2; ++mt)
            #pragma unroll
            for (int nt = 0; nt < 8; ++nt)
                #pragma unroll
                for (int i = 0; i < 4; ++i) acc[mt][nt][i] = 0.f;

        // ---- GEMM1 mainloop with interleaved A staging for the next tile ----
        #pragma unroll
        for (int ks = 0; ks < 10; ++ks) {
            uint32_t a[2][4];
            #pragma unroll
            for (int mt = 0; mt < 2; ++mt)
                LDSM_X4(a[mt][0], a[mt][1], a[mt][2], a[mt][3],
                        Ab + mt * 16 * A_PITCH_B + ks * 32);
            stsA_chunk(Aother, ks);           // 1 STS.64/thread per kstep
            #pragma unroll
            for (int nt = 0; nt < 8; ++nt) {
                const uint2 bv = *(const uint2*)(Bs
                    + (((ks * 32 + nw * 8 + nt) * 32 + lane) * 8));
                #pragma unroll
                for (int mt = 0; mt < 2; ++mt)
                    mma_f16(acc[mt][nt], a[mt], bv.x, bv.y);
            }
        }

        // ---- GEMM2 on tensor pipe (registers + constant smem only) ----
        float acc2[2][4];
        #pragma unroll
        for (int mt = 0; mt < 2; ++mt)
            #pragma unroll
            for (int i = 0; i < 4; ++i) acc2[mt][i] = 0.f;

        #pragma unroll
        for (int ks2 = 0; ks2 < 4; ++ks2) {
            const int c0 = nw * 64 + ks2 * 16 + tig * 2;
            const float bb0 = b1s[c0],     bb1 = b1s[c0 + 1];
            const float bb2 = b1s[c0 + 8], bb3 = b1s[c0 + 9];
            const uint2 bv = *(const uint2*)(W2Fs + ((nw * 4 + ks2) * 32 + lane) * 8);
            #pragma unroll
            for (int mt = 0; mt < 2; ++mt) {
                const float* p0 = acc[mt][2 * ks2];
                const float* p1 = acc[mt][2 * ks2 + 1];
                uint32_t af[4];
                af[0] = h2u(__floats2half2_rn(fmaxf(p0[0] + bb0, 0.f),
                                              fmaxf(p0[1] + bb1, 0.f)));
                af[1] = h2u(__floats2half2_rn(fmaxf(p0[2] + bb0, 0.f),
                                              fmaxf(p0[3] + bb1, 0.f)));
                af[2] = h2u(__floats2half2_rn(fmaxf(p1[0] + bb2, 0.f),
                                              fmaxf(p1[1] + bb3, 0.f)));
                af[3] = h2u(__floats2half2_rn(fmaxf(p1[2] + bb2, 0.f),
                                              fmaxf(p1[3] + bb3, 0.f)));
                mma_f16(acc2[mt], af, bv.x, bv.y);
            }
        }

        // qpart stores
        if (tig < 2) {
            #pragma unroll
            for (int mt = 0; mt < 2; ++mt) {
                const int row0 = mw * 32 + mt * 16 + gid;
                qpart[(nw * 128 + row0) * 4 + tig * 2]     = acc2[mt][0];
                qpart[(nw * 128 + row0) * 4 + tig * 2 + 1] = acc2[mt][1];
                qpart[(nw * 128 + row0 + 8) * 4 + tig * 2]     = acc2[mt][2];
                qpart[(nw * 128 + row0 + 8) * 4 + tig * 2 + 1] = acc2[mt][3];
            }
        }
        if (tid == 0) stile[0] = atomicAdd(&d_tilectr[br], 1);
        // prefetch A for the tile after next (consumed a mainloop from now)
        const bool more = (nxt < NTILES);
        __syncthreads();                      // bar1: qpart + stile published
        const int nn = stile[0];
        if (more) ldgA(nn);

        // ---- fused reduce + quantum: 4 threads/row, 512 = 128x4 ----
        {
            const int row = tid >> 2, q = tid & 3;
            float s = 0.f;
            #pragma unroll
            for (int ww = 0; ww < 4; ++ww) s += qpart[(ww * 128 + row) * 4 + q];
            const float qin = s + b2s[q];

            float cc, ssn;
            __sincosf(0.5f * qin, &ssn, &cc);
            float csc[4], css[4];
            #pragma unroll
            for (int k = 0; k < 4; ++k) {
                csc[k] = __shfl_xor_sync(0xffffffffu, cc,  q ^ k);
                css[k] = __shfl_xor_sync(0xffffffffu, ssn, q ^ k);
            }
            float v[16];
            #pragma unroll
            for (int idx = 0; idx < 16; ++idx)
                v[idx] = ((idx & 8) ? css[0] : csc[0])
                       * ((idx & 4) ? css[1] : csc[1])
                       * ((idx & 2) ? css[2] : csc[2])
                       * ((idx & 1) ? css[3] : csc[3]);
            float qo = 0.f;
            #pragma unroll
            for (int ii = 0; ii < 4; ++ii) {
                const int i = q * 4 + ii;
                float mv = 0.f;
                #pragma unroll
                for (int j = 0; j < 16; ++j)
                    mv = fmaf(Ms[i * 17 + j], v[j], mv);
                qo = fmaf(v[i], mv, qo);
            }
            qo += __shfl_xor_sync(0xffffffffu, qo, 1);
            qo += __shfl_xor_sync(0xffffffffu, qo, 2);
            if (q == 0)
                out[br * B_TOTAL + rowbase + row] = fmaf(qo, pp[0], pp[1]);
        }

        if (!more) break;
        cur = nxt; nxt = nn; p ^= 1;
        __syncthreads();                      // bar2: A buffers + qpart reuse
    }
}

extern "C" void kernel_launch(void* const* d_in, const int* in_sizes, int n_in,
                              void* d_out, int out_size) {
    const float* state  = (const float*)d_in[0];
    const float* action = (const float*)d_in[1];
    const float* q1_W1  = (const float*)d_in[2];
    const float* q1_b1  = (const float*)d_in[3];
    const float* q1_W2  = (const float*)d_in[4];
    const float* q1_b2  = (const float*)d_in[5];
    const float* q2_W1  = (const float*)d_in[6];
    const float* q2_b1  = (const float*)d_in[7];
    const float* q2_W2  = (const float*)d_in[8];
    const float* q2_b2  = (const float*)d_in[9];
    const float* q1_qw  = (const float*)d_in[10];
    const float* q2_qw  = (const float*)d_in[11];
    const float* q1_pw  = (const float*)d_in[12];
    const float* q1_pb  = (const float*)d_in[13];
    const float* q2_pw  = (const float*)d_in[14];
    const float* q2_pb  = (const float*)d_in[15];
    float* out = (float*)d_out;

    int dev = 0, nsm = 148;
    cudaGetDevice(&dev);
    cudaDeviceGetAttribute(&nsm, cudaDevAttrMultiProcessorCount, dev);
    if (nsm < 2) nsm = 2;

    cudaFuncSetAttribute(critic_mma, cudaFuncAttributeMaxDynamicSharedMemorySize,
                         SMEM_BYTES);

    setup_kernel<<<83, 256>>>(q1_qw, q2_qw, q1_W1, q2_W1, q1_W2, q2_W2);
    critic_mma<<<nsm, NTHREADS, SMEM_BYTES>>>(
        state, action,
        q1_b1, q1_b2,
        q2_b1, q2_b2,
        q1_pw, q1_pb, q2_pw, q2_pb,
        out);
}

// round 12
// speedup vs baseline: 1.1846x; 1.1846x over previous
#include <cuda_runtime.h>
#include <cuda_fp16.h>
#include <math.h>
#include <cstdint>

#define B_TOTAL 131072
#define SD 128
#define AD 32
#define TILE_M 64
#define NTILES 2048            // per branch
#define NTHREADS 256

__device__ float d_M[2][256];
// fp16 B fragments GEMM1: [br][ks(10)][ntile(32)][lane(32)][2 regs] as half2
__device__ __half2 d_Bfrag[2 * 10 * 32 * 32 * 2];
// fp16 B fragments GEMM2 (W2^T, n=8 padded): [br][ks(16)][lane(32)][2] half2
__device__ __half2 d_W2frag[2 * 16 * 32 * 2];

// ---- smem layout (byte offsets), per CTA ----
#define OFF_B     0            // 81920B: full W1 frags
#define OFF_A     81920        // [64][168] halfs = 21504B (single buffer)
#define OFF_W2F   103424       // 4096B
#define OFF_B1S   107520       // 256 floats = 1024B
#define OFF_MS    108544       // 16x17 floats -> 1152B reserved
#define OFF_QPART 109696       // fp16 qpart, double buffered: 2*4*64*2*4B = 4096B
#define OFF_B2S   113792       // 16B
#define OFF_PP    113808       // 8B
#define SMEM_BYTES 113824      // x2 CTAs = 227648 <= 228KB

#define A_PITCH 168            // halfs per row (160 data + 8 pad)
#define A_PITCH_B 336          // bytes

__device__ __forceinline__ uint32_t smem_u32(const void* p) {
    uint32_t a;
    asm("{ .reg .u64 t; cvta.to.shared.u64 t, %1; cvt.u32.u64 %0, t; }" : "=r"(a) : "l"(p));
    return a;
}
#define CP_ASYNC16(dst, src) \
    asm volatile("cp.async.cg.shared.global [%0], [%1], 16;" :: "r"(dst), "l"(src) : "memory")
#define CP_COMMIT() asm volatile("cp.async.commit_group;" ::: "memory")
#define CP_WAIT0()  asm volatile("cp.async.wait_group 0;" ::: "memory")

#define LDSM_X4(r0, r1, r2, r3, addr) \
    asm volatile("ldmatrix.sync.aligned.m8n8.x4.shared.b16 {%0,%1,%2,%3}, [%4];" \
        : "=r"(r0), "=r"(r1), "=r"(r2), "=r"(r3) : "r"(addr))

__device__ __forceinline__ void mma_f16(float* d, const uint32_t* a,
                                        uint32_t b0, uint32_t b1) {
    asm volatile(
        "mma.sync.aligned.m16n8k16.row.col.f32.f16.f16.f32 "
        "{%0,%1,%2,%3}, {%4,%5,%6,%7}, {%8,%9}, {%0,%1,%2,%3};"
        : "+f"(d[0]), "+f"(d[1]), "+f"(d[2]), "+f"(d[3])
        : "r"(a[0]), "r"(a[1]), "r"(a[2]), "r"(a[3]), "r"(b0), "r"(b1));
}
__device__ __forceinline__ uint32_t h2u(__half2 h) { return *(uint32_t*)&h; }

// ---------------------------------------------------------------------------
// Setup: blocks 0,1 -> M; 2..81 -> W1 frags; 82 -> W2 frags.
// ---------------------------------------------------------------------------
__global__ void setup_kernel(const float* __restrict__ qw1,
                             const float* __restrict__ qw2,
                             const float* __restrict__ W1a,
                             const float* __restrict__ W1b,
                             const float* __restrict__ W2a,
                             const float* __restrict__ W2b) {
    if (blockIdx.x < 2) {
        const int br = blockIdx.x;
        const int t  = threadIdx.x;
        const int j  = t >> 4;
        const int m  = t & 15;
        const float* qw = br ? qw2 : qw1;
        __shared__ float Ur[16][17];
        __shared__ float Ui[16][17];

        float sr = (m == j) ? 1.f : 0.f;
        float si = 0.f;

        for (int l = 0; l < 2; ++l) {
            #pragma unroll
            for (int i = 0; i < 4; ++i) {
                const int st = 8 >> i;
                float cc, ss, pr, pi;
                sincosf(0.5f * qw[(l * 4 + i) * 3 + 0], &ss, &cc);   // RX
                pr = __shfl_xor_sync(0xffffffffu, sr, st);
                pi = __shfl_xor_sync(0xffffffffu, si, st);
                { float nr = cc * sr + ss * pi, ni = cc * si - ss * pr;
                  sr = nr; si = ni; }
                sincosf(0.5f * qw[(l * 4 + i) * 3 + 1], &ss, &cc);   // RY
                pr = __shfl_xor_sync(0xffffffffu, sr, st);
                pi = __shfl_xor_sync(0xffffffffu, si, st);
                { const float e = (m & st) ? ss : -ss;
                  float nr = cc * sr + e * pr, ni = cc * si + e * pi;
                  sr = nr; si = ni; }
                sincosf(0.5f * qw[(l * 4 + i) * 3 + 2], &ss, &cc);   // RZ
                { const float e = (m & st) ? -ss : ss;
                  float nr = cc * sr + e * si, ni = cc * si - e * sr;
                  sr = nr; si = ni; }
            }
            #pragma unroll
            for (int e = 0; e < 4; ++e) {
                const int sc  = 8 >> e;
                const int stt = 8 >> ((e + 1) & 3);
                const float pr = __shfl_xor_sync(0xffffffffu, sr, stt);
                const float pi = __shfl_xor_sync(0xffffffffu, si, stt);
                if (m & sc) { sr = pr; si = pi; }
            }
        }
        Ur[m][j] = sr;
        Ui[m][j] = si;
        __syncthreads();
        {
            const int i = t >> 4, jj = t & 15;
            float acc = 0.f;
            #pragma unroll
            for (int k = 0; k < 16; ++k) {
                const float d = (k < 8) ? 1.f : -1.f;
                acc += d * (Ur[k][i] * Ur[k][jj] + Ui[k][i] * Ui[k][jj]);
            }
            d_M[br][i * 16 + jj] = acc;
        }
    } else if (blockIdx.x < 82) {
        const int idx = (blockIdx.x - 2) * 256 + threadIdx.x;
        const int lane  = idx & 31;
        const int ntile = (idx >> 5) & 31;
        const int t     = idx >> 10;       // br*10 + ks
        const int ks    = t % 10;
        const int br    = t / 10;
        const float* W1 = br ? W1b : W1a;
        const int n  = ntile * 8 + (lane >> 2);
        const int k0 = ks * 16 + (lane & 3) * 2;
        d_Bfrag[idx * 2]     = __floats2half2_rn(W1[n * 160 + k0],     W1[n * 160 + k0 + 1]);
        d_Bfrag[idx * 2 + 1] = __floats2half2_rn(W1[n * 160 + k0 + 8], W1[n * 160 + k0 + 9]);
    } else {
        #pragma unroll
        for (int rep = 0; rep < 4; ++rep) {
            const int idx = threadIdx.x + rep * 256;   // 0..1023
            const int br   = idx >> 9;
            const int rem  = idx & 511;
            const int ks   = rem >> 5;
            const int lane = rem & 31;
            const float* W2 = br ? W2b : W2a;
            const int n  = lane >> 2;
            const int k0 = ks * 16 + (lane & 3) * 2;
            __half2 v0 = __floats2half2_rn(0.f, 0.f), v1 = v0;
            if (n < 4) {
                v0 = __floats2half2_rn(W2[n * 256 + k0],     W2[n * 256 + k0 + 1]);
                v1 = __floats2half2_rn(W2[n * 256 + k0 + 8], W2[n * 256 + k0 + 9]);
            }
            d_W2frag[idx * 2]     = v0;
            d_W2frag[idx * 2 + 1] = v1;
        }
    }
}

// ---------------------------------------------------------------------------
// Persistent fused critic, 2 CTAs/SM. R8 base + 2 barriers/tile + reduce
// overlapped with next mainloop + ldgA hoisted into mainloop + __sincosf.
// ---------------------------------------------------------------------------
__global__ __launch_bounds__(NTHREADS, 2)
void critic_mma(const float* __restrict__ state,
                const float* __restrict__ action,
                const float* __restrict__ b1a, const float* __restrict__ b2a,
                const float* __restrict__ b1b, const float* __restrict__ b2b,
                const float* __restrict__ pwa, const float* __restrict__ pba,
                const float* __restrict__ pwb, const float* __restrict__ pbb,
                float* __restrict__ out) {
    extern __shared__ char smem[];
    const uint32_t sb = smem_u32(smem);
    const int tid  = threadIdx.x;
    const int w    = tid >> 5;
    const int lane = tid & 31;
    const int mw   = w >> 2;        // 0..1
    const int nw   = w & 3;         // 0..3
    const int gid  = lane >> 2;
    const int tig  = lane & 3;

    const int br   = blockIdx.x & 1;
    const int cid  = blockIdx.x >> 1;
    const int ncta = gridDim.x >> 1;
    const int per  = NTILES / ncta;
    const int rem  = NTILES % ncta;
    const int t0   = cid * per + (cid < rem ? cid : rem);
    const int cnt  = per + (cid < rem ? 1 : 0);

    const float* b1 = br ? b1b : b1a;
    const float* b2 = br ? b2b : b2a;
    const float* pw = br ? pwb : pwa;
    const float* pb = br ? pbb : pba;

    float*   b1s    = (float*)(smem + OFF_B1S);
    float*   Ms     = (float*)(smem + OFF_MS);      // pitch 17
    __half2* qpart2 = (__half2*)(smem + OFF_QPART); // [2][4][64][2] half2
    float*   b2s    = (float*)(smem + OFF_B2S);
    float*   pp     = (float*)(smem + OFF_PP);
    __half*  As     = (__half*)(smem + OFF_A);

    // --- A staging: 64 x 160 fp32 -> regs -> fp16 smem ---
    float4 aregs[10];
    auto ldgA = [&](int rowbase) {
        #pragma unroll
        for (int ch = 0; ch < 5; ++ch)
            #pragma unroll
            for (int i = 0; i < 2; ++i) {
                const int e = tid + i * NTHREADS;     // 0..511
                const int r = e >> 3, seg = e & 7;    // 64 rows x 8 segs
                const float* src = (ch < 4)
                    ? state  + (size_t)(rowbase + r) * SD + ch * 32 + seg * 4
                    : action + (size_t)(rowbase + r) * AD + seg * 4;
                aregs[ch * 2 + i] = *(const float4*)src;
            }
    };
    auto stsA = [&]() {
        #pragma unroll
        for (int ch = 0; ch < 5; ++ch)
            #pragma unroll
            for (int i = 0; i < 2; ++i) {
                const int e = tid + i * NTHREADS;
                const int r = e >> 3, seg = e & 7;
                const float4 v = aregs[ch * 2 + i];
                __half2 h0 = __floats2half2_rn(v.x, v.y);
                __half2 h1 = __floats2half2_rn(v.z, v.w);
                *(uint2*)(As + r * A_PITCH + ch * 32 + seg * 4) =
                    make_uint2(h2u(h0), h2u(h1));
            }
    };

    // --- prologue: B frags (80KB), W2 frags, tables, A(tile0) ---
    {
        const __half2* srcB = d_Bfrag + (size_t)br * 20480;
        #pragma unroll
        for (int i = 0; i < 20; ++i) {
            const int e = tid + i * NTHREADS;         // 0..5119 16B segs
            CP_ASYNC16(sb + OFF_B + e * 16, srcB + e * 4);
        }
        CP_ASYNC16(sb + OFF_W2F + tid * 16, d_W2frag + br * 1024 + tid * 4);
        CP_COMMIT();
    }
    ldgA(t0 * TILE_M);
    stsA();
    b1s[tid] = b1[tid];
    Ms[(tid >> 4) * 17 + (tid & 15)] = d_M[br][tid];
    if (tid < 4) b2s[tid] = b2[tid];
    if (tid == 0) { pp[0] = pw[0]; pp[1] = pb[0]; }
    CP_WAIT0();
    __syncthreads();

    const char* Bs   = smem + OFF_B;
    const char* W2Fs = smem + OFF_W2F;

    // ldmatrix per-lane address pieces
    const uint32_t lrow  = (lane & 7) + (((lane >> 3) & 1) << 3);
    const uint32_t lkofs = (lane >> 4) * 16;   // bytes
    const uint32_t Ab0 = sb + OFF_A + (mw * 32 + lrow) * A_PITCH_B + lkofs;

    int p = 0;
    for (int it = 0; it < cnt; ++it) {
        const int rowbase = (t0 + it) * TILE_M;
        const int nrb = (it + 1 < cnt) ? (t0 + it + 1) * TILE_M : rowbase;

        float acc[2][8][4];
        #pragma unroll
        for (int mt = 0; mt < 2; ++mt)
            #pragma unroll
            for (int nt = 0; nt < 8; ++nt)
                #pragma unroll
                for (int i = 0; i < 4; ++i) acc[mt][nt][i] = 0.f;

        // ---- GEMM1: 10 ksteps, barrier-free; ldgA(next) issued at ks 7 ----
        #pragma unroll
        for (int ks = 0; ks < 10; ++ks) {
            if (ks == 7) ldgA(nrb);           // LDG latency covered by ks7-9 + GEMM2
            uint32_t a[2][4];
            #pragma unroll
            for (int mt = 0; mt < 2; ++mt)
                LDSM_X4(a[mt][0], a[mt][1], a[mt][2], a[mt][3],
                        Ab0 + mt * 16 * A_PITCH_B + ks * 32);
            #pragma unroll
            for (int nt = 0; nt < 8; ++nt) {
                const uint2 bv = *(const uint2*)(Bs
                    + (((ks * 32 + nw * 8 + nt) * 32 + lane) * 8));
                #pragma unroll
                for (int mt = 0; mt < 2; ++mt)
                    mma_f16(acc[mt][nt], a[mt], bv.x, bv.y);
            }
        }
        __syncthreads();     // bar1: all A reads done; qpart[p] free (2 tiles old)

        // ---- GEMM2 on tensor pipe: h = relu(acc + b1) in fp16 ----
        float acc2[2][4];
        #pragma unroll
        for (int mt = 0; mt < 2; ++mt)
            #pragma unroll
            for (int i = 0; i < 4; ++i) acc2[mt][i] = 0.f;

        #pragma unroll
        for (int ks2 = 0; ks2 < 4; ++ks2) {
            const int c0 = nw * 64 + ks2 * 16 + tig * 2;
            const float bb0 = b1s[c0],     bb1 = b1s[c0 + 1];
            const float bb2 = b1s[c0 + 8], bb3 = b1s[c0 + 9];
            const uint2 bv = *(const uint2*)(W2Fs + ((nw * 4 + ks2) * 32 + lane) * 8);
            #pragma unroll
            for (int mt = 0; mt < 2; ++mt) {
                const float* p0 = acc[mt][2 * ks2];
                const float* p1 = acc[mt][2 * ks2 + 1];
                uint32_t af[4];
                af[0] = h2u(__floats2half2_rn(fmaxf(p0[0] + bb0, 0.f),
                                              fmaxf(p0[1] + bb1, 0.f)));
                af[1] = h2u(__floats2half2_rn(fmaxf(p0[2] + bb0, 0.f),
                                              fmaxf(p0[3] + bb1, 0.f)));
                af[2] = h2u(__floats2half2_rn(fmaxf(p1[0] + bb2, 0.f),
                                              fmaxf(p1[1] + bb3, 0.f)));
                af[3] = h2u(__floats2half2_rn(fmaxf(p1[2] + bb2, 0.f),
                                              fmaxf(p1[3] + bb3, 0.f)));
                mma_f16(acc2[mt], af, bv.x, bv.y);
            }
        }

        // stage next tile's A (LDG data arriving; readers blocked until bar2)
        stsA();

        // qpart[p] stores (fp16 pairs): thread (tig<2) holds q = 2tig, 2tig+1
        if (tig < 2) {
            #pragma unroll
            for (int mt = 0; mt < 2; ++mt) {
                const int row0 = mw * 32 + mt * 16 + gid;
                qpart2[((p * 4 + nw) * 64 + row0) * 2 + tig] =
                    __floats2half2_rn(acc2[mt][0], acc2[mt][1]);
                qpart2[((p * 4 + nw) * 64 + row0 + 8) * 2 + tig] =
                    __floats2half2_rn(acc2[mt][2], acc2[mt][3]);
            }
        }
        __syncthreads();     // bar2: publishes qpart[p] + staged A

        // ---- fused reduce + quantum; overlaps next tile's mainloop ----
        {
            const int row = tid >> 2, q = tid & 3;
            float s = 0.f;
            #pragma unroll
            for (int ww = 0; ww < 4; ++ww) {
                const __half2 v = qpart2[((p * 4 + ww) * 64 + row) * 2 + (q >> 1)];
                s += (q & 1) ? __high2float(v) : __low2float(v);
            }
            const float qin = s + b2s[q];

            float cc, ssn;
            __sincosf(0.5f * qin, &ssn, &cc);
            float csc[4], css[4];
            #pragma unroll
            for (int k = 0; k < 4; ++k) {
                csc[k] = __shfl_xor_sync(0xffffffffu, cc,  q ^ k);
                css[k] = __shfl_xor_sync(0xffffffffu, ssn, q ^ k);
            }
            float v[16];
            #pragma unroll
            for (int idx = 0; idx < 16; ++idx)
                v[idx] = ((idx & 8) ? css[0] : csc[0])
                       * ((idx & 4) ? css[1] : csc[1])
                       * ((idx & 2) ? css[2] : csc[2])
                       * ((idx & 1) ? css[3] : csc[3]);
            float qo = 0.f;
            #pragma unroll
            for (int ii = 0; ii < 4; ++ii) {
                const int i = q * 4 + ii;
                float mv = 0.f;
                #pragma unroll
                for (int j = 0; j < 16; ++j)
                    mv = fmaf(Ms[i * 17 + j], v[j], mv);
                qo = fmaf(v[i], mv, qo);
            }
            qo += __shfl_xor_sync(0xffffffffu, qo, 1);
            qo += __shfl_xor_sync(0xffffffffu, qo, 2);
            if (q == 0)
                out[br * B_TOTAL + rowbase + row] = fmaf(qo, pp[0], pp[1]);
        }
        p ^= 1;
    }
}

extern "C" void kernel_launch(void* const* d_in, const int* in_sizes, int n_in,
                              void* d_out, int out_size) {
    const float* state  = (const float*)d_in[0];
    const float* action = (const float*)d_in[1];
    const float* q1_W1  = (const float*)d_in[2];
    const float* q1_b1  = (const float*)d_in[3];
    const float* q1_W2  = (const float*)d_in[4];
    const float* q1_b2  = (const float*)d_in[5];
    const float* q2_W1  = (const float*)d_in[6];
    const float* q2_b1  = (const float*)d_in[7];
    const float* q2_W2  = (const float*)d_in[8];
    const float* q2_b2  = (const float*)d_in[9];
    const float* q1_qw  = (const float*)d_in[10];
    const float* q2_qw  = (const float*)d_in[11];
    const float* q1_pw  = (const float*)d_in[12];
    const float* q1_pb  = (const float*)d_in[13];
    const float* q2_pw  = (const float*)d_in[14];
    const float* q2_pb  = (const float*)d_in[15];
    float* out = (float*)d_out;

    int dev = 0, nsm = 148;
    cudaGetDevice(&dev);
    cudaDeviceGetAttribute(&nsm, cudaDevAttrMultiProcessorCount, dev);
    if (nsm < 1) nsm = 1;

    cudaFuncSetAttribute(critic_mma, cudaFuncAttributeMaxDynamicSharedMemorySize,
                         SMEM_BYTES);

    setup_kernel<<<83, 256>>>(q1_qw, q2_qw, q1_W1, q2_W1, q1_W2, q2_W2);
    critic_mma<<<2 * nsm, NTHREADS, SMEM_BYTES>>>(
        state, action,
        q1_b1, q1_b2,
        q2_b1, q2_b2,
        q1_pw, q1_pb, q2_pw, q2_pb,
        out);
}

// round 13
// speedup vs baseline: 1.2050x; 1.0173x over previous
#include <cuda_runtime.h>
#include <cuda_fp16.h>
#include <math.h>
#include <cstdint>

#define B_TOTAL 131072
#define SD 128
#define AD 32
#define TILE_M 64
#define NTILES 2048            // per branch
#define NTHREADS 256

__device__ float d_M[2][256];
// fp16 B fragments GEMM1: [br][ks(10)][ntile(32)][lane(32)][2 regs] as half2
__device__ __half2 d_Bfrag[2 * 10 * 32 * 32 * 2];
// fp16 B fragments GEMM2 (W2^T, n=8 padded): [br][ks(16)][lane(32)][2] half2
__device__ __half2 d_W2frag[2 * 16 * 32 * 2];

// ---- smem layout (byte offsets), per CTA ----
#define OFF_B     0            // 81920B: full W1 frags
#define OFF_A     81920        // [64][168] halfs = 21504B (single buffer)
#define OFF_W2F   103424       // 4096B
#define OFF_B1S   107520       // 256 floats = 1024B
#define OFF_MS    108544       // 16x17 floats -> 1152B reserved
#define OFF_QPART 109696       // fp16 qpart, double buffered: 2*4*64*2*4B = 4096B
#define OFF_B2S   113792       // 16B
#define OFF_PP    113808       // 8B
#define SMEM_BYTES 113824      // x2 CTAs = 227648 <= 228KB

#define A_PITCH 168            // halfs per row (160 data + 8 pad)
#define A_PITCH_B 336          // bytes

__device__ __forceinline__ uint32_t smem_u32(const void* p) {
    uint32_t a;
    asm("{ .reg .u64 t; cvta.to.shared.u64 t, %1; cvt.u32.u64 %0, t; }" : "=r"(a) : "l"(p));
    return a;
}
#define CP_ASYNC16(dst, src) \
    asm volatile("cp.async.cg.shared.global [%0], [%1], 16;" :: "r"(dst), "l"(src) : "memory")
#define CP_COMMIT() asm volatile("cp.async.commit_group;" ::: "memory")
#define CP_WAIT0()  asm volatile("cp.async.wait_group 0;" ::: "memory")

#define LDSM_X4(r0, r1, r2, r3, addr) \
    asm volatile("ldmatrix.sync.aligned.m8n8.x4.shared.b16 {%0,%1,%2,%3}, [%4];" \
        : "=r"(r0), "=r"(r1), "=r"(r2), "=r"(r3) : "r"(addr))

__device__ __forceinline__ void mma_f16(float* d, const uint32_t* a,
                                        uint32_t b0, uint32_t b1) {
    asm volatile(
        "mma.sync.aligned.m16n8k16.row.col.f32.f16.f16.f32 "
        "{%0,%1,%2,%3}, {%4,%5,%6,%7}, {%8,%9}, {%0,%1,%2,%3};"
        : "+f"(d[0]), "+f"(d[1]), "+f"(d[2]), "+f"(d[3])
        : "r"(a[0]), "r"(a[1]), "r"(a[2]), "r"(a[3]), "r"(b0), "r"(b1));
}
__device__ __forceinline__ uint32_t h2u(__half2 h) { return *(uint32_t*)&h; }

// ---------------------------------------------------------------------------
// Setup: blocks 0,1 -> M; 2..81 -> W1 frags; 82 -> W2 frags.
// ---------------------------------------------------------------------------
__global__ void setup_kernel(const float* __restrict__ qw1,
                             const float* __restrict__ qw2,
                             const float* __restrict__ W1a,
                             const float* __restrict__ W1b,
                             const float* __restrict__ W2a,
                             const float* __restrict__ W2b) {
    if (blockIdx.x < 2) {
        const int br = blockIdx.x;
        const int t  = threadIdx.x;
        const int j  = t >> 4;
        const int m  = t & 15;
        const float* qw = br ? qw2 : qw1;
        __shared__ float Ur[16][17];
        __shared__ float Ui[16][17];

        float sr = (m == j) ? 1.f : 0.f;
        float si = 0.f;

        for (int l = 0; l < 2; ++l) {
            #pragma unroll
            for (int i = 0; i < 4; ++i) {
                const int st = 8 >> i;
                float cc, ss, pr, pi;
                sincosf(0.5f * qw[(l * 4 + i) * 3 + 0], &ss, &cc);   // RX
                pr = __shfl_xor_sync(0xffffffffu, sr, st);
                pi = __shfl_xor_sync(0xffffffffu, si, st);
                { float nr = cc * sr + ss * pi, ni = cc * si - ss * pr;
                  sr = nr; si = ni; }
                sincosf(0.5f * qw[(l * 4 + i) * 3 + 1], &ss, &cc);   // RY
                pr = __shfl_xor_sync(0xffffffffu, sr, st);
                pi = __shfl_xor_sync(0xffffffffu, si, st);
                { const float e = (m & st) ? ss : -ss;
                  float nr = cc * sr + e * pr, ni = cc * si + e * pi;
                  sr = nr; si = ni; }
                sincosf(0.5f * qw[(l * 4 + i) * 3 + 2], &ss, &cc);   // RZ
                { const float e = (m & st) ? -ss : ss;
                  float nr = cc * sr + e * si, ni = cc * si - e * sr;
                  sr = nr; si = ni; }
            }
            #pragma unroll
            for (int e = 0; e < 4; ++e) {
                const int sc  = 8 >> e;
                const int stt = 8 >> ((e + 1) & 3);
                const float pr = __shfl_xor_sync(0xffffffffu, sr, stt);
                const float pi = __shfl_xor_sync(0xffffffffu, si, stt);
                if (m & sc) { sr = pr; si = pi; }
            }
        }
        Ur[m][j] = sr;
        Ui[m][j] = si;
        __syncthreads();
        {
            const int i = t >> 4, jj = t & 15;
            float acc = 0.f;
            #pragma unroll
            for (int k = 0; k < 16; ++k) {
                const float d = (k < 8) ? 1.f : -1.f;
                acc += d * (Ur[k][i] * Ur[k][jj] + Ui[k][i] * Ui[k][jj]);
            }
            d_M[br][i * 16 + jj] = acc;
        }
    } else if (blockIdx.x < 82) {
        const int idx = (blockIdx.x - 2) * 256 + threadIdx.x;
        const int lane  = idx & 31;
        const int ntile = (idx >> 5) & 31;
        const int t     = idx >> 10;       // br*10 + ks
        const int ks    = t % 10;
        const int br    = t / 10;
        const float* W1 = br ? W1b : W1a;
        const int n  = ntile * 8 + (lane >> 2);
        const int k0 = ks * 16 + (lane & 3) * 2;
        d_Bfrag[idx * 2]     = __floats2half2_rn(W1[n * 160 + k0],     W1[n * 160 + k0 + 1]);
        d_Bfrag[idx * 2 + 1] = __floats2half2_rn(W1[n * 160 + k0 + 8], W1[n * 160 + k0 + 9]);
    } else {
        #pragma unroll
        for (int rep = 0; rep < 4; ++rep) {
            const int idx = threadIdx.x + rep * 256;   // 0..1023
            const int br   = idx >> 9;
            const int rem  = idx & 511;
            const int ks   = rem >> 5;
            const int lane = rem & 31;
            const float* W2 = br ? W2b : W2a;
            const int n  = lane >> 2;
            const int k0 = ks * 16 + (lane & 3) * 2;
            __half2 v0 = __floats2half2_rn(0.f, 0.f), v1 = v0;
            if (n < 4) {
                v0 = __floats2half2_rn(W2[n * 256 + k0],     W2[n * 256 + k0 + 1]);
                v1 = __floats2half2_rn(W2[n * 256 + k0 + 8], W2[n * 256 + k0 + 9]);
            }
            d_W2frag[idx * 2]     = v0;
            d_W2frag[idx * 2 + 1] = v1;
        }
    }
}

// ---------------------------------------------------------------------------
// Persistent fused critic, 2 CTAs/SM. R12 base + GEMM2 hoisted before bar1
// (absorbs barrier skew with useful work) + split acc2 dependency chains.
// ---------------------------------------------------------------------------
__global__ __launch_bounds__(NTHREADS, 2)
void critic_mma(const float* __restrict__ state,
                const float* __restrict__ action,
                const float* __restrict__ b1a, const float* __restrict__ b2a,
                const float* __restrict__ b1b, const float* __restrict__ b2b,
                const float* __restrict__ pwa, const float* __restrict__ pba,
                const float* __restrict__ pwb, const float* __restrict__ pbb,
                float* __restrict__ out) {
    extern __shared__ char smem[];
    const uint32_t sb = smem_u32(smem);
    const int tid  = threadIdx.x;
    const int w    = tid >> 5;
    const int lane = tid & 31;
    const int mw   = w >> 2;        // 0..1
    const int nw   = w & 3;         // 0..3
    const int gid  = lane >> 2;
    const int tig  = lane & 3;

    const int br   = blockIdx.x & 1;
    const int cid  = blockIdx.x >> 1;
    const int ncta = gridDim.x >> 1;
    const int per  = NTILES / ncta;
    const int rem  = NTILES % ncta;
    const int t0   = cid * per + (cid < rem ? cid : rem);
    const int cnt  = per + (cid < rem ? 1 : 0);

    const float* b1 = br ? b1b : b1a;
    const float* b2 = br ? b2b : b2a;
    const float* pw = br ? pwb : pwa;
    const float* pb = br ? pbb : pba;

    float*   b1s    = (float*)(smem + OFF_B1S);
    float*   Ms     = (float*)(smem + OFF_MS);      // pitch 17
    __half2* qpart2 = (__half2*)(smem + OFF_QPART); // [2][4][64][2] half2
    float*   b2s    = (float*)(smem + OFF_B2S);
    float*   pp     = (float*)(smem + OFF_PP);
    __half*  As     = (__half*)(smem + OFF_A);

    // --- A staging: 64 x 160 fp32 -> regs -> fp16 smem ---
    float4 aregs[10];
    auto ldgA = [&](int rowbase) {
        #pragma unroll
        for (int ch = 0; ch < 5; ++ch)
            #pragma unroll
            for (int i = 0; i < 2; ++i) {
                const int e = tid + i * NTHREADS;     // 0..511
                const int r = e >> 3, seg = e & 7;    // 64 rows x 8 segs
                const float* src = (ch < 4)
                    ? state  + (size_t)(rowbase + r) * SD + ch * 32 + seg * 4
                    : action + (size_t)(rowbase + r) * AD + seg * 4;
                aregs[ch * 2 + i] = *(const float4*)src;
            }
    };
    auto stsA = [&]() {
        #pragma unroll
        for (int ch = 0; ch < 5; ++ch)
            #pragma unroll
            for (int i = 0; i < 2; ++i) {
                const int e = tid + i * NTHREADS;
                const int r = e >> 3, seg = e & 7;
                const float4 v = aregs[ch * 2 + i];
                __half2 h0 = __floats2half2_rn(v.x, v.y);
                __half2 h1 = __floats2half2_rn(v.z, v.w);
                *(uint2*)(As + r * A_PITCH + ch * 32 + seg * 4) =
                    make_uint2(h2u(h0), h2u(h1));
            }
    };

    // --- prologue: B frags (80KB), W2 frags, tables, A(tile0) ---
    {
        const __half2* srcB = d_Bfrag + (size_t)br * 20480;
        #pragma unroll
        for (int i = 0; i < 20; ++i) {
            const int e = tid + i * NTHREADS;         // 0..5119 16B segs
            CP_ASYNC16(sb + OFF_B + e * 16, srcB + e * 4);
        }
        CP_ASYNC16(sb + OFF_W2F + tid * 16, d_W2frag + br * 1024 + tid * 4);
        CP_COMMIT();
    }
    ldgA(t0 * TILE_M);
    stsA();
    b1s[tid] = b1[tid];
    Ms[(tid >> 4) * 17 + (tid & 15)] = d_M[br][tid];
    if (tid < 4) b2s[tid] = b2[tid];
    if (tid == 0) { pp[0] = pw[0]; pp[1] = pb[0]; }
    CP_WAIT0();
    __syncthreads();

    const char* Bs   = smem + OFF_B;
    const char* W2Fs = smem + OFF_W2F;

    // ldmatrix per-lane address pieces
    const uint32_t lrow  = (lane & 7) + (((lane >> 3) & 1) << 3);
    const uint32_t lkofs = (lane >> 4) * 16;   // bytes
    const uint32_t Ab0 = sb + OFF_A + (mw * 32 + lrow) * A_PITCH_B + lkofs;

    int p = 0;
    for (int it = 0; it < cnt; ++it) {
        const int rowbase = (t0 + it) * TILE_M;
        const int nrb = (it + 1 < cnt) ? (t0 + it + 1) * TILE_M : rowbase;

        float acc[2][8][4];
        #pragma unroll
        for (int mt = 0; mt < 2; ++mt)
            #pragma unroll
            for (int nt = 0; nt < 8; ++nt)
                #pragma unroll
                for (int i = 0; i < 4; ++i) acc[mt][nt][i] = 0.f;

        // ---- GEMM1: 10 ksteps, barrier-free; ldgA(next) issued at ks 7 ----
        #pragma unroll
        for (int ks = 0; ks < 10; ++ks) {
            if (ks == 7) ldgA(nrb);           // LDG latency covered by ks7-9 + GEMM2
            uint32_t a[2][4];
            #pragma unroll
            for (int mt = 0; mt < 2; ++mt)
                LDSM_X4(a[mt][0], a[mt][1], a[mt][2], a[mt][3],
                        Ab0 + mt * 16 * A_PITCH_B + ks * 32);
            #pragma unroll
            for (int nt = 0; nt < 8; ++nt) {
                const uint2 bv = *(const uint2*)(Bs
                    + (((ks * 32 + nw * 8 + nt) * 32 + lane) * 8));
                #pragma unroll
                for (int mt = 0; mt < 2; ++mt)
                    mma_f16(acc[mt][nt], a[mt], bv.x, bv.y);
            }
        }

        // ---- GEMM2 (registers + constant smem only — needs NO barrier;
        //      absorbs barrier-arrival skew). Two independent acc chains. ----
        float acc2a[2][4], acc2b[2][4];
        #pragma unroll
        for (int mt = 0; mt < 2; ++mt)
            #pragma unroll
            for (int i = 0; i < 4; ++i) { acc2a[mt][i] = 0.f; acc2b[mt][i] = 0.f; }

        #pragma unroll
        for (int ks2 = 0; ks2 < 4; ++ks2) {
            const int c0 = nw * 64 + ks2 * 16 + tig * 2;
            const float bb0 = b1s[c0],     bb1 = b1s[c0 + 1];
            const float bb2 = b1s[c0 + 8], bb3 = b1s[c0 + 9];
            const uint2 bv = *(const uint2*)(W2Fs + ((nw * 4 + ks2) * 32 + lane) * 8);
            #pragma unroll
            for (int mt = 0; mt < 2; ++mt) {
                const float* p0 = acc[mt][2 * ks2];
                const float* p1 = acc[mt][2 * ks2 + 1];
                uint32_t af[4];
                af[0] = h2u(__floats2half2_rn(fmaxf(p0[0] + bb0, 0.f),
                                              fmaxf(p0[1] + bb1, 0.f)));
                af[1] = h2u(__floats2half2_rn(fmaxf(p0[2] + bb0, 0.f),
                                              fmaxf(p0[3] + bb1, 0.f)));
                af[2] = h2u(__floats2half2_rn(fmaxf(p1[0] + bb2, 0.f),
                                              fmaxf(p1[1] + bb3, 0.f)));
                af[3] = h2u(__floats2half2_rn(fmaxf(p1[2] + bb2, 0.f),
                                              fmaxf(p1[3] + bb3, 0.f)));
                if (ks2 & 1) mma_f16(acc2b[mt], af, bv.x, bv.y);
                else         mma_f16(acc2a[mt], af, bv.x, bv.y);
            }
        }

        __syncthreads();     // bar1: A reads done; qpart[p] free (2 tiles old)

        // stage next tile's A
        stsA();

        // qpart[p] stores (fp16 pairs): thread (tig<2) holds q = 2tig, 2tig+1
        if (tig < 2) {
            #pragma unroll
            for (int mt = 0; mt < 2; ++mt) {
                const int row0 = mw * 32 + mt * 16 + gid;
                qpart2[((p * 4 + nw) * 64 + row0) * 2 + tig] =
                    __floats2half2_rn(acc2a[mt][0] + acc2b[mt][0],
                                      acc2a[mt][1] + acc2b[mt][1]);
                qpart2[((p * 4 + nw) * 64 + row0 + 8) * 2 + tig] =
                    __floats2half2_rn(acc2a[mt][2] + acc2b[mt][2],
                                      acc2a[mt][3] + acc2b[mt][3]);
            }
        }
        __syncthreads();     // bar2: publishes qpart[p] + staged A

        // ---- fused reduce + quantum; overlaps next tile's mainloop ----
        {
            const int row = tid >> 2, q = tid & 3;
            float s = 0.f;
            #pragma unroll
            for (int ww = 0; ww < 4; ++ww) {
                const __half2 v = qpart2[((p * 4 + ww) * 64 + row) * 2 + (q >> 1)];
                s += (q & 1) ? __high2float(v) : __low2float(v);
            }
            const float qin = s + b2s[q];

            float cc, ssn;
            __sincosf(0.5f * qin, &ssn, &cc);
            float csc[4], css[4];
            #pragma unroll
            for (int k = 0; k < 4; ++k) {
                csc[k] = __shfl_xor_sync(0xffffffffu, cc,  q ^ k);
                css[k] = __shfl_xor_sync(0xffffffffu, ssn, q ^ k);
            }
            float v[16];
            #pragma unroll
            for (int idx = 0; idx < 16; ++idx)
                v[idx] = ((idx & 8) ? css[0] : csc[0])
                       * ((idx & 4) ? css[1] : csc[1])
                       * ((idx & 2) ? css[2] : csc[2])
                       * ((idx & 1) ? css[3] : csc[3]);
            float qo = 0.f;
            #pragma unroll
            for (int ii = 0; ii < 4; ++ii) {
                const int i = q * 4 + ii;
                float mv = 0.f;
                #pragma unroll
                for (int j = 0; j < 16; ++j)
                    mv = fmaf(Ms[i * 17 + j], v[j], mv);
                qo = fmaf(v[i], mv, qo);
            }
            qo += __shfl_xor_sync(0xffffffffu, qo, 1);
            qo += __shfl_xor_sync(0xffffffffu, qo, 2);
            if (q == 0)
                out[br * B_TOTAL + rowbase + row] = fmaf(qo, pp[0], pp[1]);
        }
        p ^= 1;
    }
}

extern "C" void kernel_launch(void* const* d_in, const int* in_sizes, int n_in,
                              void* d_out, int out_size) {
    const float* state  = (const float*)d_in[0];
    const float* action = (const float*)d_in[1];
    const float* q1_W1  = (const float*)d_in[2];
    const float* q1_b1  = (const float*)d_in[3];
    const float* q1_W2  = (const float*)d_in[4];
    const float* q1_b2  = (const float*)d_in[5];
    const float* q2_W1  = (const float*)d_in[6];
    const float* q2_b1  = (const float*)d_in[7];
    const float* q2_W2  = (const float*)d_in[8];
    const float* q2_b2  = (const float*)d_in[9];
    const float* q1_qw  = (const float*)d_in[10];
    const float* q2_qw  = (const float*)d_in[11];
    const float* q1_pw  = (const float*)d_in[12];
    const float* q1_pb  = (const float*)d_in[13];
    const float* q2_pw  = (const float*)d_in[14];
    const float* q2_pb  = (const float*)d_in[15];
    float* out = (float*)d_out;

    int dev = 0, nsm = 148;
    cudaGetDevice(&dev);
    cudaDeviceGetAttribute(&nsm, cudaDevAttrMultiProcessorCount, dev);
    if (nsm < 1) nsm = 1;

    cudaFuncSetAttribute(critic_mma, cudaFuncAttributeMaxDynamicSharedMemorySize,
                         SMEM_BYTES);

    setup_kernel<<<83, 256>>>(q1_qw, q2_qw, q1_W1, q2_W1, q1_W2, q2_W2);
    critic_mma<<<2 * nsm, NTHREADS, SMEM_BYTES>>>(
        state, action,
        q1_b1, q1_b2,
        q2_b1, q2_b2,
        q1_pw, q1_pb, q2_pw, q2_pb,
        out);
}